// round 8
// baseline (speedup 1.0000x reference)
#include <cuda_runtime.h>

#define IMG 512
#define TW 32
#define TH 32
#define IW 42
#define IH 42
#define HROW 34
#define PL (IH * HROW)            // 1428 floats per hh plane
#define NPIX (16LL * 3 * 512 * 512)
#define GRID_X 16
#define GRID_Y 16
#define GRID_Z 48
#define GRID_TOTAL (GRID_X * GRID_Y * GRID_Z)
#define NBUCKET 64
#define BSTRIDE 32                 // doubles; 256B spacing between buckets
#define QUOTA (GRID_TOTAL / NBUCKET)   // 192

typedef unsigned long long u64;

__device__ double g_buckets[NBUCKET * BSTRIDE];   // zero-init; reset each run
__device__ unsigned int g_cnt[NBUCKET * 64];      // 256B-strided counters
__device__ unsigned int g_cnt2;

// Gaussian(sigma=1.5, K=11) weights, normalized — compile-time constants.
#define WV0 0.00102838f
#define WV1 0.00759876f
#define WV2 0.03600077f
#define WV3 0.10936069f
#define WV4 0.21300553f
#define WV5 0.26601172f
__device__ __forceinline__ float wv(int t) {
    switch (t) {
        case 0: case 10: return WV0;
        case 1: case 9:  return WV1;
        case 2: case 8:  return WV2;
        case 3: case 7:  return WV3;
        case 4: case 6:  return WV4;
        default:         return WV5;
    }
}

__device__ __forceinline__ u64 pack2(float lo, float hi) {
    u64 r; asm("mov.b64 %0,{%1,%2};" : "=l"(r) : "f"(lo), "f"(hi)); return r;
}
__device__ __forceinline__ void unpack2(u64 v, float& lo, float& hi) {
    asm("mov.b64 {%0,%1},%2;" : "=f"(lo), "=f"(hi) : "l"(v));
}
__device__ __forceinline__ u64 fma2(u64 a, u64 b, u64 c) {
    u64 d; asm("fma.rn.f32x2 %0,%1,%2,%3;" : "=l"(d) : "l"(a), "l"(b), "l"(c)); return d;
}
__device__ __forceinline__ u64 mul2(u64 a, u64 b) {
    u64 d; asm("mul.rn.f32x2 %0,%1,%2;" : "=l"(d) : "l"(a), "l"(b)); return d;
}
__device__ __forceinline__ u64 add2(u64 a, u64 b) {
    u64 d; asm("add.rn.f32x2 %0,%1,%2;" : "=l"(d) : "l"(a), "l"(b)); return d;
}

__global__ __launch_bounds__(256, 4) void ssim_kernel(
    const float* __restrict__ A, const float* __restrict__ B,
    float* __restrict__ out)
{
    __shared__ __align__(16) float sA[IH][IW];
    __shared__ __align__(16) float sB[IH][IW];
    __shared__ __align__(16) float hh[4][IH][HROW];   // A, B, A^2+B^2, AB
    __shared__ float wsum[8];
    __shared__ int final_flag;
    __shared__ double dtmp[64];

    const int tid = threadIdx.x;
    const int plane = blockIdx.z;
    const int tx0 = blockIdx.x * TW;
    const int ty0 = blockIdx.y * TH;
    const float* a = A + (size_t)plane * IMG * IMG;
    const float* b = B + (size_t)plane * IMG * IMG;

    // ---- Stage haloed 42x42 tile, zero-padded ----
    float* sAf = &sA[0][0];
    float* sBf = &sB[0][0];
    for (int idx = tid; idx < IH * IW; idx += 256) {
        int r = idx / IW;
        int c = idx - r * IW;
        int gy = ty0 - 5 + r;
        int gx = tx0 - 5 + c;
        float va = 0.f, vb = 0.f;
        if (gy >= 0 && gy < IMG && gx >= 0 && gx < IMG) {
            size_t o = (size_t)gy * IMG + gx;
            va = __ldg(a + o);
            vb = __ldg(b + o);
        }
        sAf[idx] = va;
        sBf[idx] = vb;
    }
    __syncthreads();

    // Packed (duplicated) weights for the f32x2 horizontal pass.
    const u64 W0p = pack2(WV0, WV0), W1p = pack2(WV1, WV1), W2p = pack2(WV2, WV2);
    const u64 W3p = pack2(WV3, WV3), W4p = pack2(WV4, WV4), W5p = pack2(WV5, WV5);

    // Even/odd aligned-pair horizontal 11-tap conv: 4 outputs per call.
    auto hplane = [&](const u64* q, float* dst) {
        u64 E2a = fma2(W0p, add2(q[0], q[5]),
                  fma2(W2p, add2(q[1], q[4]),
                  mul2(W4p, add2(q[2], q[3]))));
        u64 E2b = fma2(W0p, add2(q[1], q[6]),
                  fma2(W2p, add2(q[2], q[5]),
                  mul2(W4p, add2(q[3], q[4]))));
        u64 Oa  = fma2(W1p, add2(q[0], q[4]),
                  fma2(W3p, add2(q[1], q[3]), mul2(W5p, q[2])));
        u64 Ob  = fma2(W1p, add2(q[1], q[5]),
                  fma2(W3p, add2(q[2], q[4]), mul2(W5p, q[3])));
        u64 Oc  = fma2(W1p, add2(q[2], q[6]),
                  fma2(W3p, add2(q[3], q[5]), mul2(W5p, q[4])));
        float oal, oah, obl, obh, ocl, och;
        unpack2(Oa, oal, oah);
        unpack2(Ob, obl, obh);
        unpack2(Oc, ocl, och);
        *(u64*)(dst)     = add2(E2a, pack2(oah, obl));
        *(u64*)(dst + 2) = add2(E2b, pack2(obh, ocl));
    };

    // ---- Horizontal pass: 42 rows x 8 groups of 4 outputs (336 items) ----
    for (int g = tid; g < IH * 8; g += 256) {
        int r = g >> 3;
        int c0 = (g & 7) << 2;
        const float* rowA = &sA[r][c0];
        const float* rowB = &sB[r][c0];
        float* dst = &hh[0][r][c0];
        u64 qa[7], qb[7];
#pragma unroll
        for (int j = 0; j < 7; j++) qa[j] = *(const u64*)(rowA + 2 * j);
#pragma unroll
        for (int j = 0; j < 7; j++) qb[j] = *(const u64*)(rowB + 2 * j);
        hplane(qa, dst);                                  // A
        hplane(qb, dst + PL);                             // B
#pragma unroll
        for (int j = 0; j < 7; j++) {
            u64 ab = mul2(qa[j], qb[j]);
            qb[j] = fma2(qb[j], qb[j], mul2(qa[j], qa[j]));
            qa[j] = ab;
        }
        hplane(qb, dst + 2 * PL);                         // A^2 + B^2
        hplane(qa, dst + 3 * PL);                         // AB
    }
    __syncthreads();

    // ---- Vertical pass: 256 threads, each 1 col x 4 rows, single sweep ----
    const float C1 = 0.0001f;
    const float C2 = 0.0009f;
    float accf = 0.f;
    {
        int c = tid & 31;
        int rg = tid >> 5;
        const float* hp = &hh[0][rg * 4][c];

        float m1[4], m2[4], ss[4], e12[4];
#pragma unroll
        for (int i = 0; i < 4; i++) { m1[i] = m2[i] = ss[i] = e12[i] = 0.f; }

#pragma unroll
        for (int k = 0; k < 14; k++) {
            float v0 = hp[k * HROW];
            float v1 = hp[k * HROW + PL];
            float v2 = hp[k * HROW + 2 * PL];
            float v3 = hp[k * HROW + 3 * PL];
#pragma unroll
            for (int i = 0; i < 4; i++) {
                int t = k - i;
                if (t >= 0 && t <= 10) {
                    float w = wv(t);
                    m1[i]  += w * v0;
                    m2[i]  += w * v1;
                    ss[i]  += w * v2;
                    e12[i] += w * v3;
                }
            }
        }

#pragma unroll
        for (int i = 0; i < 4; i++) {
            float m1s = m1[i] * m1[i];
            float m2s = m2[i] * m2[i];
            float m12 = m1[i] * m2[i];
            float mss = m1s + m2s;
            float p2  = m12 + m12;
            float t2  = e12[i] + e12[i];
            float n1  = p2 + C1;
            float n2  = (t2 - p2) + C2;
            float d1  = mss + C1;
            float d2  = (ss[i] - mss) + C2;
            accf += __fdividef(n1 * n2, d1 * d2);
        }
    }

    // ---- Block reduction ----
#pragma unroll
    for (int off = 16; off > 0; off >>= 1)
        accf += __shfl_down_sync(0xffffffffu, accf, off);
    if ((tid & 31) == 0) wsum[tid >> 5] = accf;
    __syncthreads();

    // ---- Bucketized global reduction (64 buckets, 256B strided) ----
    const int bid = (blockIdx.z * GRID_Y + blockIdx.y) * GRID_X + blockIdx.x;
    const int slot = bid & (NBUCKET - 1);
    if (tid == 0) {
        float bsum = 0.f;
#pragma unroll
        for (int i = 0; i < 8; i++) bsum += wsum[i];
        atomicAdd(&g_buckets[slot * BSTRIDE], (double)bsum);
        __threadfence();
        unsigned int c = atomicAdd(&g_cnt[slot * 64], 1u);
        int fin = 0;
        if (c == QUOTA - 1) {                       // bucket leader
            atomicExch(&g_cnt[slot * 64], 0u);      // reset for next replay
            __threadfence();
            unsigned int c2 = atomicAdd(&g_cnt2, 1u);
            if (c2 == NBUCKET - 1) fin = 1;         // last bucket -> finalize
        }
        final_flag = fin;
    }
    __syncthreads();

    if (final_flag) {
        // Parallel drain: 64 lanes exchange-and-zero the buckets.
        __threadfence();
        if (tid < NBUCKET) {
            u64 old = atomicExch(
                (unsigned long long*)&g_buckets[tid * BSTRIDE], 0ull);
            dtmp[tid] = __longlong_as_double(old);
        }
        __syncthreads();
        if (tid < 8) {
            double s = 0.0;
#pragma unroll
            for (int i = 0; i < 8; i++) s += dtmp[tid * 8 + i];
            dtmp[tid] = s;
        }
        __syncthreads();
        if (tid == 0) {
            double s = 0.0;
#pragma unroll
            for (int i = 0; i < 8; i++) s += dtmp[i];
            out[0] = (float)(s / (double)NPIX);
            atomicExch(&g_cnt2, 0u);                // reset for next replay
            __threadfence();
        }
    }
}

extern "C" void kernel_launch(void* const* d_in, const int* in_sizes, int n_in,
                              void* d_out, int out_size)
{
    const float* A = (const float*)d_in[0];
    const float* B = (const float*)d_in[1];
    float* out = (float*)d_out;
    dim3 grid(GRID_X, GRID_Y, GRID_Z);
    ssim_kernel<<<grid, 256>>>(A, B, out);
}

// round 9
// speedup vs baseline: 1.0383x; 1.0383x over previous
#include <cuda_runtime.h>

#define IMG 512
#define TW 32
#define TH 32
#define IW 42
#define IH 42
#define HROW 34
#define PL (IH * HROW)            // 1428 floats per hh plane
#define NPIX (16LL * 3 * 512 * 512)
#define GRID_X 16
#define GRID_Y 16
#define GRID_Z 48
#define GRID_TOTAL (GRID_X * GRID_Y * GRID_Z)

typedef unsigned long long u64;

__device__ double g_sum;
__device__ unsigned int g_count;

// Gaussian(sigma=1.5, K=11) weights, normalized — compile-time constants.
#define WV0 0.00102838f
#define WV1 0.00759876f
#define WV2 0.03600077f
#define WV3 0.10936069f
#define WV4 0.21300553f
#define WV5 0.26601172f

__device__ __forceinline__ u64 pack2(float lo, float hi) {
    u64 r; asm("mov.b64 %0,{%1,%2};" : "=l"(r) : "f"(lo), "f"(hi)); return r;
}
__device__ __forceinline__ void unpack2(u64 v, float& lo, float& hi) {
    asm("mov.b64 {%0,%1},%2;" : "=f"(lo), "=f"(hi) : "l"(v));
}
__device__ __forceinline__ u64 fma2(u64 a, u64 b, u64 c) {
    u64 d; asm("fma.rn.f32x2 %0,%1,%2,%3;" : "=l"(d) : "l"(a), "l"(b), "l"(c)); return d;
}
__device__ __forceinline__ u64 mul2(u64 a, u64 b) {
    u64 d; asm("mul.rn.f32x2 %0,%1,%2;" : "=l"(d) : "l"(a), "l"(b)); return d;
}
__device__ __forceinline__ u64 add2(u64 a, u64 b) {
    u64 d; asm("add.rn.f32x2 %0,%1,%2;" : "=l"(d) : "l"(a), "l"(b)); return d;
}
__device__ __forceinline__ u64 sub2(u64 a, u64 b) {
    u64 d; asm("sub.rn.f32x2 %0,%1,%2;" : "=l"(d) : "l"(a), "l"(b)); return d;
}

__global__ __launch_bounds__(256, 4) void ssim_kernel(
    const float* __restrict__ A, const float* __restrict__ B,
    float* __restrict__ out)
{
    __shared__ __align__(16) float sA[IH][IW];
    __shared__ __align__(16) float sB[IH][IW];
    __shared__ __align__(16) float hh[4][IH][HROW];   // A, B, A^2+B^2, AB
    __shared__ float wsum[8];

    const int tid = threadIdx.x;
    const int plane = blockIdx.z;
    const int tx0 = blockIdx.x * TW;
    const int ty0 = blockIdx.y * TH;
    const float* a = A + (size_t)plane * IMG * IMG;
    const float* b = B + (size_t)plane * IMG * IMG;

    // ---- Stage haloed 42x42 tile, zero-padded ----
    float* sAf = &sA[0][0];
    float* sBf = &sB[0][0];
    for (int idx = tid; idx < IH * IW; idx += 256) {
        int r = idx / IW;
        int c = idx - r * IW;
        int gy = ty0 - 5 + r;
        int gx = tx0 - 5 + c;
        float va = 0.f, vb = 0.f;
        if (gy >= 0 && gy < IMG && gx >= 0 && gx < IMG) {
            size_t o = (size_t)gy * IMG + gx;
            va = __ldg(a + o);
            vb = __ldg(b + o);
        }
        sAf[idx] = va;
        sBf[idx] = vb;
    }
    __syncthreads();

    // Packed (duplicated) weights.
    const u64 W0p = pack2(WV0, WV0), W1p = pack2(WV1, WV1), W2p = pack2(WV2, WV2);
    const u64 W3p = pack2(WV3, WV3), W4p = pack2(WV4, WV4), W5p = pack2(WV5, WV5);

    auto wp = [&](int t) -> u64 {
        switch (t) {
            case 0: case 10: return W0p;
            case 1: case 9:  return W1p;
            case 2: case 8:  return W2p;
            case 3: case 7:  return W3p;
            case 4: case 6:  return W4p;
            default:         return W5p;
        }
    };

    // Even/odd aligned-pair horizontal 11-tap conv: 4 outputs per call.
    auto hplane = [&](const u64* q, float* dst) {
        u64 E2a = fma2(W0p, add2(q[0], q[5]),
                  fma2(W2p, add2(q[1], q[4]),
                  mul2(W4p, add2(q[2], q[3]))));
        u64 E2b = fma2(W0p, add2(q[1], q[6]),
                  fma2(W2p, add2(q[2], q[5]),
                  mul2(W4p, add2(q[3], q[4]))));
        u64 Oa  = fma2(W1p, add2(q[0], q[4]),
                  fma2(W3p, add2(q[1], q[3]), mul2(W5p, q[2])));
        u64 Ob  = fma2(W1p, add2(q[1], q[5]),
                  fma2(W3p, add2(q[2], q[4]), mul2(W5p, q[3])));
        u64 Oc  = fma2(W1p, add2(q[2], q[6]),
                  fma2(W3p, add2(q[3], q[5]), mul2(W5p, q[4])));
        float oal, oah, obl, obh, ocl, och;
        unpack2(Oa, oal, oah);
        unpack2(Ob, obl, obh);
        unpack2(Oc, ocl, och);
        *(u64*)(dst)     = add2(E2a, pack2(oah, obl));
        *(u64*)(dst + 2) = add2(E2b, pack2(obh, ocl));
    };

    // ---- Horizontal pass: 42 rows x 8 groups of 4 outputs (336 items) ----
    for (int g = tid; g < IH * 8; g += 256) {
        int r = g >> 3;
        int c0 = (g & 7) << 2;
        const float* rowA = &sA[r][c0];
        const float* rowB = &sB[r][c0];
        float* dst = &hh[0][r][c0];
        u64 qa[7], qb[7];
#pragma unroll
        for (int j = 0; j < 7; j++) qa[j] = *(const u64*)(rowA + 2 * j);
#pragma unroll
        for (int j = 0; j < 7; j++) qb[j] = *(const u64*)(rowB + 2 * j);
        hplane(qa, dst);                                  // A
        hplane(qb, dst + PL);                             // B
#pragma unroll
        for (int j = 0; j < 7; j++) {
            u64 ab = mul2(qa[j], qb[j]);
            qb[j] = fma2(qb[j], qb[j], mul2(qa[j], qa[j]));
            qa[j] = ab;
        }
        hplane(qb, dst + 2 * PL);                         // A^2 + B^2
        hplane(qa, dst + 3 * PL);                         // AB
    }
    __syncthreads();

    // ---- Vertical pass: 128 threads, each 2 cols x 4 rows, single sweep,
    //      f32x2 packed over 4 planes ----
    const float C1 = 0.0001f;
    const float C2 = 0.0009f;
    float accf = 0.f;
    if (tid < 128) {
        int xp = tid & 15;        // column pair 0..15
        int rg = tid >> 4;        // row group 0..7 (4 rows each)
        const float* hp = &hh[0][rg * 4][2 * xp];

        u64 zero = pack2(0.f, 0.f);
        u64 m1[4], m2[4], ss[4], e12[4];
#pragma unroll
        for (int i = 0; i < 4; i++) { m1[i] = m2[i] = ss[i] = e12[i] = zero; }

#pragma unroll
        for (int k = 0; k < 14; k++) {
            u64 L0 = *(const u64*)(hp + k * HROW);
            u64 L1 = *(const u64*)(hp + k * HROW + PL);
            u64 L2 = *(const u64*)(hp + k * HROW + 2 * PL);
            u64 L3 = *(const u64*)(hp + k * HROW + 3 * PL);
#pragma unroll
            for (int i = 0; i < 4; i++) {
                int t = k - i;
                if (t >= 0 && t <= 10) {
                    u64 w = wp(t);
                    m1[i]  = fma2(w, L0, m1[i]);
                    m2[i]  = fma2(w, L1, m2[i]);
                    ss[i]  = fma2(w, L2, ss[i]);
                    e12[i] = fma2(w, L3, e12[i]);
                }
            }
        }

        const u64 c1p = pack2(C1, C1);
        const u64 c2p = pack2(C2, C2);
#pragma unroll
        for (int i = 0; i < 4; i++) {
            u64 m1s = mul2(m1[i], m1[i]);
            u64 m2s = mul2(m2[i], m2[i]);
            u64 m12 = mul2(m1[i], m2[i]);
            u64 mss = add2(m1s, m2s);
            u64 p2  = add2(m12, m12);
            u64 t2  = add2(e12[i], e12[i]);
            u64 n1  = add2(p2, c1p);
            u64 n2  = add2(sub2(t2, p2), c2p);
            u64 d1  = add2(mss, c1p);
            u64 d2  = add2(sub2(ss[i], mss), c2p);
            u64 num = mul2(n1, n2);
            u64 den = mul2(d1, d2);
            float nx, ny, dx, dy;
            unpack2(num, nx, ny);
            unpack2(den, dx, dy);
            accf += __fdividef(nx, dx) + __fdividef(ny, dy);
        }
    }

    // ---- Block reduction + single-pass finalize ----
#pragma unroll
    for (int off = 16; off > 0; off >>= 1)
        accf += __shfl_down_sync(0xffffffffu, accf, off);
    if ((tid & 31) == 0) wsum[tid >> 5] = accf;
    __syncthreads();
    if (tid == 0) {
        float bsum = 0.f;
#pragma unroll
        for (int i = 0; i < 8; i++) bsum += wsum[i];
        atomicAdd(&g_sum, (double)bsum);
        __threadfence();
        unsigned int cold = atomicAdd(&g_count, 1u);
        if (cold == GRID_TOTAL - 1) {
            __threadfence();
            double s = *((volatile double*)&g_sum);
            out[0] = (float)(s / (double)NPIX);
            g_sum = 0.0;
            g_count = 0u;
            __threadfence();
        }
    }
}

extern "C" void kernel_launch(void* const* d_in, const int* in_sizes, int n_in,
                              void* d_out, int out_size)
{
    const float* A = (const float*)d_in[0];
    const float* B = (const float*)d_in[1];
    float* out = (float*)d_out;
    dim3 grid(GRID_X, GRID_Y, GRID_Z);
    ssim_kernel<<<grid, 256>>>(A, B, out);
}

// round 10
// speedup vs baseline: 1.5268x; 1.4704x over previous
#include <cuda_runtime.h>

#define IMG 512
#define TW 32
#define TH 32
#define IW 42
#define IH 42
#define HROW 34
#define PL (IH * HROW)            // 1428 floats per hh plane
#define NPIX (16LL * 3 * 512 * 512)
#define GRID_X 16
#define GRID_Y 16
#define GRID_Z 48
#define GRID_TOTAL (GRID_X * GRID_Y * GRID_Z)

typedef unsigned long long u64;

__device__ double g_sum;
__device__ unsigned int g_count;

// Gaussian(sigma=1.5, K=11) weights, normalized — compile-time constants.
#define WV0 0.00102838f
#define WV1 0.00759876f
#define WV2 0.03600077f
#define WV3 0.10936069f
#define WV4 0.21300553f
#define WV5 0.26601172f

__device__ __forceinline__ u64 pack2(float lo, float hi) {
    u64 r; asm("mov.b64 %0,{%1,%2};" : "=l"(r) : "f"(lo), "f"(hi)); return r;
}
__device__ __forceinline__ void unpack2(u64 v, float& lo, float& hi) {
    asm("mov.b64 {%0,%1},%2;" : "=f"(lo), "=f"(hi) : "l"(v));
}
__device__ __forceinline__ u64 fma2(u64 a, u64 b, u64 c) {
    u64 d; asm("fma.rn.f32x2 %0,%1,%2,%3;" : "=l"(d) : "l"(a), "l"(b), "l"(c)); return d;
}
__device__ __forceinline__ u64 mul2(u64 a, u64 b) {
    u64 d; asm("mul.rn.f32x2 %0,%1,%2;" : "=l"(d) : "l"(a), "l"(b)); return d;
}
__device__ __forceinline__ u64 add2(u64 a, u64 b) {
    u64 d; asm("add.rn.f32x2 %0,%1,%2;" : "=l"(d) : "l"(a), "l"(b)); return d;
}
__device__ __forceinline__ u64 sub2(u64 a, u64 b) {
    u64 d; asm("sub.rn.f32x2 %0,%1,%2;" : "=l"(d) : "l"(a), "l"(b)); return d;
}

__global__ __launch_bounds__(256, 4) void ssim_kernel(
    const float* __restrict__ A, const float* __restrict__ B,
    float* __restrict__ out)
{
    __shared__ __align__(16) float sA[IH][IW];
    __shared__ __align__(16) float sB[IH][IW];
    __shared__ __align__(16) float hh[4][IH][HROW];   // A, B, A^2+B^2, AB
    __shared__ float wsum[8];

    const int tid = threadIdx.x;
    const int plane = blockIdx.z;
    const int tx0 = blockIdx.x * TW;
    const int ty0 = blockIdx.y * TH;
    const float* a = A + (size_t)plane * IMG * IMG;
    const float* b = B + (size_t)plane * IMG * IMG;

    // ---- Stage haloed 42x42 tile, zero-padded. Fully unrolled, all LDGs
    //      issued before any STS (MLP=14) so DRAM latency is paid once. ----
    float* sAf = &sA[0][0];
    float* sBf = &sB[0][0];
    {
        float va[7], vb[7];
#pragma unroll
        for (int j = 0; j < 7; j++) {
            int idx = tid + j * 256;
            int r = idx / IW;
            int c = idx - r * IW;
            int gy = ty0 - 5 + r;
            int gx = tx0 - 5 + c;
            bool ok = (idx < IH * IW) &&
                      (gy >= 0) && (gy < IMG) && (gx >= 0) && (gx < IMG);
            size_t o = (size_t)(gy * IMG + gx);
            va[j] = 0.f;
            vb[j] = 0.f;
            if (ok) {
                va[j] = __ldg(a + o);
                vb[j] = __ldg(b + o);
            }
        }
#pragma unroll
        for (int j = 0; j < 7; j++) {
            int idx = tid + j * 256;
            if (idx < IH * IW) {
                sAf[idx] = va[j];
                sBf[idx] = vb[j];
            }
        }
    }
    __syncthreads();

    // Packed (duplicated) weights.
    const u64 W0p = pack2(WV0, WV0), W1p = pack2(WV1, WV1), W2p = pack2(WV2, WV2);
    const u64 W3p = pack2(WV3, WV3), W4p = pack2(WV4, WV4), W5p = pack2(WV5, WV5);

    auto wp = [&](int t) -> u64 {
        switch (t) {
            case 0: case 10: return W0p;
            case 1: case 9:  return W1p;
            case 2: case 8:  return W2p;
            case 3: case 7:  return W3p;
            case 4: case 6:  return W4p;
            default:         return W5p;
        }
    };

    // Even/odd aligned-pair horizontal 11-tap conv: 4 outputs per call.
    auto hplane = [&](const u64* q, float* dst) {
        u64 E2a = fma2(W0p, add2(q[0], q[5]),
                  fma2(W2p, add2(q[1], q[4]),
                  mul2(W4p, add2(q[2], q[3]))));
        u64 E2b = fma2(W0p, add2(q[1], q[6]),
                  fma2(W2p, add2(q[2], q[5]),
                  mul2(W4p, add2(q[3], q[4]))));
        u64 Oa  = fma2(W1p, add2(q[0], q[4]),
                  fma2(W3p, add2(q[1], q[3]), mul2(W5p, q[2])));
        u64 Ob  = fma2(W1p, add2(q[1], q[5]),
                  fma2(W3p, add2(q[2], q[4]), mul2(W5p, q[3])));
        u64 Oc  = fma2(W1p, add2(q[2], q[6]),
                  fma2(W3p, add2(q[3], q[5]), mul2(W5p, q[4])));
        float oal, oah, obl, obh, ocl, och;
        unpack2(Oa, oal, oah);
        unpack2(Ob, obl, obh);
        unpack2(Oc, ocl, och);
        *(u64*)(dst)     = add2(E2a, pack2(oah, obl));
        *(u64*)(dst + 2) = add2(E2b, pack2(obh, ocl));
    };

    // ---- Horizontal pass: 42 rows x 8 groups of 4 outputs (336 items) ----
    for (int g = tid; g < IH * 8; g += 256) {
        int r = g >> 3;
        int c0 = (g & 7) << 2;
        const float* rowA = &sA[r][c0];
        const float* rowB = &sB[r][c0];
        float* dst = &hh[0][r][c0];
        u64 qa[7], qb[7];
#pragma unroll
        for (int j = 0; j < 7; j++) qa[j] = *(const u64*)(rowA + 2 * j);
#pragma unroll
        for (int j = 0; j < 7; j++) qb[j] = *(const u64*)(rowB + 2 * j);
        hplane(qa, dst);                                  // A
        hplane(qb, dst + PL);                             // B
#pragma unroll
        for (int j = 0; j < 7; j++) {
            u64 ab = mul2(qa[j], qb[j]);
            qb[j] = fma2(qb[j], qb[j], mul2(qa[j], qa[j]));
            qa[j] = ab;
        }
        hplane(qb, dst + 2 * PL);                         // A^2 + B^2
        hplane(qa, dst + 3 * PL);                         // AB
    }
    __syncthreads();

    // ---- Vertical pass: 128 threads, each 2 cols x 4 rows, single sweep,
    //      f32x2 packed over 4 planes ----
    const float C1 = 0.0001f;
    const float C2 = 0.0009f;
    float accf = 0.f;
    if (tid < 128) {
        int xp = tid & 15;        // column pair 0..15
        int rg = tid >> 4;        // row group 0..7 (4 rows each)
        const float* hp = &hh[0][rg * 4][2 * xp];

        u64 zero = pack2(0.f, 0.f);
        u64 m1[4], m2[4], ss[4], e12[4];
#pragma unroll
        for (int i = 0; i < 4; i++) { m1[i] = m2[i] = ss[i] = e12[i] = zero; }

#pragma unroll
        for (int k = 0; k < 14; k++) {
            u64 L0 = *(const u64*)(hp + k * HROW);
            u64 L1 = *(const u64*)(hp + k * HROW + PL);
            u64 L2 = *(const u64*)(hp + k * HROW + 2 * PL);
            u64 L3 = *(const u64*)(hp + k * HROW + 3 * PL);
#pragma unroll
            for (int i = 0; i < 4; i++) {
                int t = k - i;
                if (t >= 0 && t <= 10) {
                    u64 w = wp(t);
                    m1[i]  = fma2(w, L0, m1[i]);
                    m2[i]  = fma2(w, L1, m2[i]);
                    ss[i]  = fma2(w, L2, ss[i]);
                    e12[i] = fma2(w, L3, e12[i]);
                }
            }
        }

        const u64 c1p = pack2(C1, C1);
        const u64 c2p = pack2(C2, C2);
#pragma unroll
        for (int i = 0; i < 4; i++) {
            u64 m1s = mul2(m1[i], m1[i]);
            u64 m2s = mul2(m2[i], m2[i]);
            u64 m12 = mul2(m1[i], m2[i]);
            u64 mss = add2(m1s, m2s);
            u64 p2  = add2(m12, m12);
            u64 t2  = add2(e12[i], e12[i]);
            u64 n1  = add2(p2, c1p);
            u64 n2  = add2(sub2(t2, p2), c2p);
            u64 d1  = add2(mss, c1p);
            u64 d2  = add2(sub2(ss[i], mss), c2p);
            u64 num = mul2(n1, n2);
            u64 den = mul2(d1, d2);
            float nx, ny, dx, dy;
            unpack2(num, nx, ny);
            unpack2(den, dx, dy);
            accf += __fdividef(nx, dx) + __fdividef(ny, dy);
        }
    }

    // ---- Block reduction + single-pass finalize ----
#pragma unroll
    for (int off = 16; off > 0; off >>= 1)
        accf += __shfl_down_sync(0xffffffffu, accf, off);
    if ((tid & 31) == 0) wsum[tid >> 5] = accf;
    __syncthreads();
    if (tid == 0) {
        float bsum = 0.f;
#pragma unroll
        for (int i = 0; i < 8; i++) bsum += wsum[i];
        atomicAdd(&g_sum, (double)bsum);
        __threadfence();
        unsigned int cold = atomicAdd(&g_count, 1u);
        if (cold == GRID_TOTAL - 1) {
            __threadfence();
            double s = *((volatile double*)&g_sum);
            out[0] = (float)(s / (double)NPIX);
            g_sum = 0.0;
            g_count = 0u;
            __threadfence();
        }
    }
}

extern "C" void kernel_launch(void* const* d_in, const int* in_sizes, int n_in,
                              void* d_out, int out_size)
{
    const float* A = (const float*)d_in[0];
    const float* B = (const float*)d_in[1];
    float* out = (float*)d_out;
    dim3 grid(GRID_X, GRID_Y, GRID_Z);
    ssim_kernel<<<grid, 256>>>(A, B, out);
}

// round 11
// speedup vs baseline: 1.6036x; 1.0503x over previous
#include <cuda_runtime.h>

#define IMG 512
#define TW 32
#define TH 32
#define IW 42
#define IH 42
#define HROW 34
#define PL (IH * HROW)            // 1428 floats per hh plane
#define NPIX (16LL * 3 * 512 * 512)
#define GRID_X 16
#define GRID_Y 16
#define GRID_Z 48
#define GRID_TOTAL (GRID_X * GRID_Y * GRID_Z)

typedef unsigned long long u64;

__device__ double g_sum;
__device__ unsigned int g_count;

// Gaussian(sigma=1.5, K=11) weights, normalized — compile-time constants.
#define WV0 0.00102838f
#define WV1 0.00759876f
#define WV2 0.03600077f
#define WV3 0.10936069f
#define WV4 0.21300553f
#define WV5 0.26601172f

__device__ __forceinline__ u64 pack2(float lo, float hi) {
    u64 r; asm("mov.b64 %0,{%1,%2};" : "=l"(r) : "f"(lo), "f"(hi)); return r;
}
__device__ __forceinline__ void unpack2(u64 v, float& lo, float& hi) {
    asm("mov.b64 {%0,%1},%2;" : "=f"(lo), "=f"(hi) : "l"(v));
}
__device__ __forceinline__ u64 fma2(u64 a, u64 b, u64 c) {
    u64 d; asm("fma.rn.f32x2 %0,%1,%2,%3;" : "=l"(d) : "l"(a), "l"(b), "l"(c)); return d;
}
__device__ __forceinline__ u64 mul2(u64 a, u64 b) {
    u64 d; asm("mul.rn.f32x2 %0,%1,%2;" : "=l"(d) : "l"(a), "l"(b)); return d;
}
__device__ __forceinline__ u64 add2(u64 a, u64 b) {
    u64 d; asm("add.rn.f32x2 %0,%1,%2;" : "=l"(d) : "l"(a), "l"(b)); return d;
}
__device__ __forceinline__ u64 sub2(u64 a, u64 b) {
    u64 d; asm("sub.rn.f32x2 %0,%1,%2;" : "=l"(d) : "l"(a), "l"(b)); return d;
}

__global__ __launch_bounds__(256, 5) void ssim_kernel(
    const float* __restrict__ A, const float* __restrict__ B,
    float* __restrict__ out)
{
    __shared__ __align__(16) float sA[IH][IW];
    __shared__ __align__(16) float sB[IH][IW];
    __shared__ __align__(16) float hh[4][IH][HROW];   // A, B, A^2+B^2, AB
    __shared__ float wsum[8];

    const int tid = threadIdx.x;
    const int plane = blockIdx.z;
    const int tx0 = blockIdx.x * TW;
    const int ty0 = blockIdx.y * TH;
    const float* a = A + (size_t)plane * IMG * IMG;
    const float* b = B + (size_t)plane * IMG * IMG;

    // ---- Stage haloed 42x42 tile, zero-padded. All LDGs issued before any
    //      STS (MLP=14) so DRAM latency is paid once. ----
    float* sAf = &sA[0][0];
    float* sBf = &sB[0][0];
    {
        float va[7], vb[7];
#pragma unroll
        for (int j = 0; j < 7; j++) {
            int idx = tid + j * 256;
            int r = idx / IW;
            int c = idx - r * IW;
            int gy = ty0 - 5 + r;
            int gx = tx0 - 5 + c;
            bool ok = (idx < IH * IW) &&
                      (gy >= 0) && (gy < IMG) && (gx >= 0) && (gx < IMG);
            size_t o = (size_t)(gy * IMG + gx);
            va[j] = 0.f;
            vb[j] = 0.f;
            if (ok) {
                va[j] = __ldg(a + o);
                vb[j] = __ldg(b + o);
            }
        }
#pragma unroll
        for (int j = 0; j < 7; j++) {
            int idx = tid + j * 256;
            if (idx < IH * IW) {
                sAf[idx] = va[j];
                sBf[idx] = vb[j];
            }
        }
    }
    __syncthreads();

    // Packed (duplicated) weights.
    const u64 W0p = pack2(WV0, WV0), W1p = pack2(WV1, WV1), W2p = pack2(WV2, WV2);
    const u64 W3p = pack2(WV3, WV3), W4p = pack2(WV4, WV4), W5p = pack2(WV5, WV5);

    auto wp = [&](int t) -> u64 {
        switch (t) {
            case 0: case 10: return W0p;
            case 1: case 9:  return W1p;
            case 2: case 8:  return W2p;
            case 3: case 7:  return W3p;
            case 4: case 6:  return W4p;
            default:         return W5p;
        }
    };

    // Even/odd aligned-pair horizontal 11-tap conv: 4 outputs per call.
    auto hplane = [&](const u64* q, float* dst) {
        u64 E2a = fma2(W0p, add2(q[0], q[5]),
                  fma2(W2p, add2(q[1], q[4]),
                  mul2(W4p, add2(q[2], q[3]))));
        u64 E2b = fma2(W0p, add2(q[1], q[6]),
                  fma2(W2p, add2(q[2], q[5]),
                  mul2(W4p, add2(q[3], q[4]))));
        u64 Oa  = fma2(W1p, add2(q[0], q[4]),
                  fma2(W3p, add2(q[1], q[3]), mul2(W5p, q[2])));
        u64 Ob  = fma2(W1p, add2(q[1], q[5]),
                  fma2(W3p, add2(q[2], q[4]), mul2(W5p, q[3])));
        u64 Oc  = fma2(W1p, add2(q[2], q[6]),
                  fma2(W3p, add2(q[3], q[5]), mul2(W5p, q[4])));
        float oal, oah, obl, obh, ocl, och;
        unpack2(Oa, oal, oah);
        unpack2(Ob, obl, obh);
        unpack2(Oc, ocl, och);
        *(u64*)(dst)     = add2(E2a, pack2(oah, obl));
        *(u64*)(dst + 2) = add2(E2b, pack2(obh, ocl));
    };

    // ---- Horizontal pass: 42 rows x 8 groups of 4 outputs (336 items).
    //      Single q[] buffer (re-read for products) keeps regs ~50. ----
    for (int g = tid; g < IH * 8; g += 256) {
        int r = g >> 3;
        int c0 = (g & 7) << 2;
        const float* rowA = &sA[r][c0];
        const float* rowB = &sB[r][c0];
        float* dst = &hh[0][r][c0];
        u64 q[7];
#pragma unroll
        for (int j = 0; j < 7; j++) q[j] = *(const u64*)(rowA + 2 * j);
        hplane(q, dst);                                   // A
#pragma unroll
        for (int j = 0; j < 7; j++)
            q[j] = mul2(q[j], *(const u64*)(rowB + 2 * j));
        hplane(q, dst + 3 * PL);                          // AB
#pragma unroll
        for (int j = 0; j < 7; j++) q[j] = *(const u64*)(rowB + 2 * j);
        hplane(q, dst + PL);                              // B
#pragma unroll
        for (int j = 0; j < 7; j++) {
            u64 xa = *(const u64*)(rowA + 2 * j);
            q[j] = fma2(q[j], q[j], mul2(xa, xa));
        }
        hplane(q, dst + 2 * PL);                          // A^2 + B^2
    }
    __syncthreads();

    // ---- Vertical pass: 128 threads, each 2 cols x 4 rows, TWO sweeps of
    //      2 planes each (same total LDS as one sweep; half the live regs). ----
    const float C1 = 0.0001f;
    const float C2 = 0.0009f;
    float accf = 0.f;
    if (tid < 128) {
        int xp = tid & 15;        // column pair 0..15
        int rg = tid >> 4;        // row group 0..7 (4 rows each)
        const float* hp = &hh[0][rg * 4][2 * xp];

        u64 zero = pack2(0.f, 0.f);
        u64 m1[4], m2[4];
#pragma unroll
        for (int i = 0; i < 4; i++) { m1[i] = m2[i] = zero; }
#pragma unroll
        for (int k = 0; k < 14; k++) {
            u64 L0 = *(const u64*)(hp + k * HROW);
            u64 L1 = *(const u64*)(hp + k * HROW + PL);
#pragma unroll
            for (int i = 0; i < 4; i++) {
                int t = k - i;
                if (t >= 0 && t <= 10) {
                    u64 w = wp(t);
                    m1[i] = fma2(w, L0, m1[i]);
                    m2[i] = fma2(w, L1, m2[i]);
                }
            }
        }
        u64 ss[4], e12[4];
#pragma unroll
        for (int i = 0; i < 4; i++) { ss[i] = e12[i] = zero; }
#pragma unroll
        for (int k = 0; k < 14; k++) {
            u64 L2 = *(const u64*)(hp + k * HROW + 2 * PL);
            u64 L3 = *(const u64*)(hp + k * HROW + 3 * PL);
#pragma unroll
            for (int i = 0; i < 4; i++) {
                int t = k - i;
                if (t >= 0 && t <= 10) {
                    u64 w = wp(t);
                    ss[i]  = fma2(w, L2, ss[i]);
                    e12[i] = fma2(w, L3, e12[i]);
                }
            }
        }

        const u64 c1p = pack2(C1, C1);
        const u64 c2p = pack2(C2, C2);
#pragma unroll
        for (int i = 0; i < 4; i++) {
            u64 m1s = mul2(m1[i], m1[i]);
            u64 m2s = mul2(m2[i], m2[i]);
            u64 m12 = mul2(m1[i], m2[i]);
            u64 mss = add2(m1s, m2s);
            u64 p2  = add2(m12, m12);
            u64 t2  = add2(e12[i], e12[i]);
            u64 n1  = add2(p2, c1p);
            u64 n2  = add2(sub2(t2, p2), c2p);
            u64 d1  = add2(mss, c1p);
            u64 d2  = add2(sub2(ss[i], mss), c2p);
            u64 num = mul2(n1, n2);
            u64 den = mul2(d1, d2);
            float nx, ny, dx, dy;
            unpack2(num, nx, ny);
            unpack2(den, dx, dy);
            accf += __fdividef(nx, dx) + __fdividef(ny, dy);
        }
    }

    // ---- Block reduction + single-pass finalize ----
#pragma unroll
    for (int off = 16; off > 0; off >>= 1)
        accf += __shfl_down_sync(0xffffffffu, accf, off);
    if ((tid & 31) == 0) wsum[tid >> 5] = accf;
    __syncthreads();
    if (tid == 0) {
        float bsum = 0.f;
#pragma unroll
        for (int i = 0; i < 8; i++) bsum += wsum[i];
        atomicAdd(&g_sum, (double)bsum);
        __threadfence();
        unsigned int cold = atomicAdd(&g_count, 1u);
        if (cold == GRID_TOTAL - 1) {
            __threadfence();
            double s = *((volatile double*)&g_sum);
            out[0] = (float)(s / (double)NPIX);
            g_sum = 0.0;
            g_count = 0u;
            __threadfence();
        }
    }
}

extern "C" void kernel_launch(void* const* d_in, const int* in_sizes, int n_in,
                              void* d_out, int out_size)
{
    const float* A = (const float*)d_in[0];
    const float* B = (const float*)d_in[1];
    float* out = (float*)d_out;
    dim3 grid(GRID_X, GRID_Y, GRID_Z);
    ssim_kernel<<<grid, 256>>>(A, B, out);
}